// round 13
// baseline (speedup 1.0000x reference)
#include <cuda_runtime.h>
#include <cuda_fp16.h>
#include <cstdint>

// Problem constants
#define VOCAB 32000
#define EMB   64
#define HID   64
#define BATCH 16
#define SEQ   256
#define ROWS  (BATCH*SEQ)   // 4096
#define G3    (3*HID)       // 192
#define NCHUNK 16           // 16 chunks of 16 steps
#define WCONV_BLOCKS 2000   // 512000 float4 / 256

// GEMM tiling (R3-proven shape)
#define GM 128
#define GN 128
#define LDS_H 72                                   // halves per smem row (64+8 pad)
#define TILE_SM (GM * LDS_H * 2 + GN * LDS_H * 2)  // 36864 B
#define NTILE ((VOCAB / GN) * (ROWS / GM))   // 250*32 = 8000
#define TPB   (VOCAB / GN)                   // 250

// Launch shape: 16 GRU blocks + oversubscribed one-tile GEMM blocks
#define GEMM_GRID   12000
#define GRID_FAT    (16 + GEMM_GRID)
#define EXIT_BUDGET 3500     // guaranteed workers: 12000-3500 = 8500 > 8000

// Scratch (device globals; no allocation allowed)
__device__ float  g_xp[ROWS * G3];          // x @ w_ih^T + b_ih
__device__ __half g_hh[ROWS * HID];         // h, layout [chunk][batch][s%16][64]
__device__ __half g_wh[VOCAB * HID];        // w_out fp16
__device__ int    g_cnt[NCHUNK];            // chunk completion counters
__device__ int    g_sm_role[256];           // 1 = GRU owns this SM
__device__ int    g_marked;                 // # GRU blocks that published role
__device__ int    g_tile_ctr;               // GEMM tile claim counter
__device__ int    g_exit_ctr;               // churn budget counter

// ---------------------------------------------------------------------------
// helpers
// ---------------------------------------------------------------------------
__device__ __forceinline__ void fma2(unsigned long long& d,
                                     unsigned long long a, unsigned long long b) {
    asm("fma.rn.f32x2 %0, %1, %2, %0;" : "+l"(d) : "l"(a), "l"(b));
}
__device__ __forceinline__ float upsum(unsigned long long v) {
    unsigned lo, hi;
    asm("mov.b64 {%0,%1}, %2;" : "=r"(lo), "=r"(hi) : "l"(v));
    return __uint_as_float(lo) + __uint_as_float(hi);
}
__device__ __forceinline__ float frcp(float x) {
    float r; asm("rcp.approx.f32 %0, %1;" : "=f"(r) : "f"(x)); return r;
}
__device__ __forceinline__ float fsigm(float x) { return frcp(1.f + __expf(-x)); }
__device__ __forceinline__ float ftanh(float x) {
    return 1.f - 2.f * frcp(__expf(2.f * x) + 1.f);
}
__device__ __forceinline__ void ldsm_x4(uint32_t* r, uint32_t addr) {
    asm volatile("ldmatrix.sync.aligned.m8n8.x4.shared.b16 {%0,%1,%2,%3}, [%4];"
                 : "=r"(r[0]), "=r"(r[1]), "=r"(r[2]), "=r"(r[3]) : "r"(addr));
}
__device__ __forceinline__ void mma16816(float* d, const uint32_t* a, const uint32_t* b) {
    asm volatile(
        "mma.sync.aligned.m16n8k16.row.col.f32.f16.f16.f32 "
        "{%0,%1,%2,%3},{%4,%5,%6,%7},{%8,%9},{%0,%1,%2,%3};"
        : "+f"(d[0]), "+f"(d[1]), "+f"(d[2]), "+f"(d[3])
        : "r"(a[0]), "r"(a[1]), "r"(a[2]), "r"(a[3]), "r"(b[0]), "r"(b[1]));
}
__device__ __forceinline__ uint32_t smem_u32(const void* p) {
    uint32_t a;
    asm("{ .reg .u64 t; cvta.to.shared.u64 t, %1; cvt.u32.u64 %0, t; }"
        : "=r"(a) : "l"(p));
    return a;
}
__device__ __forceinline__ int smid() {
    int s; asm("mov.u32 %0, %%smid;" : "=r"(s)); return s;
}
// g_hh row R -> original (b,s) C row:  b = (R>>4)&15, s = (R>>8)*16 + (R&15)
__device__ __forceinline__ int crow(int R) {
    return (((R >> 4) & 15) << 8) + ((R >> 8) << 4) + (R & 15);
}

// ---------------------------------------------------------------------------
// Prep kernel: blocks [0,2000) convert w_out fp32->fp16;
// blocks [2000, 2128) embedding + input projection (+ counter resets).
// ---------------------------------------------------------------------------
__global__ __launch_bounds__(256) void prep_kernel(
    const float* __restrict__ W,
    const int* __restrict__ tokens, const float* __restrict__ emb,
    const float* __restrict__ w_ih, const float* __restrict__ b_ih)
{
    const int tid = threadIdx.x;

    if (blockIdx.x < WCONV_BLOCKS) {
        size_t i = (size_t)blockIdx.x * 256 + tid;
        float4 v = reinterpret_cast<const float4*>(W)[i];
        __half2* d = reinterpret_cast<__half2*>(g_wh + i * 4);
        d[0] = __floats2half2_rn(v.x, v.y);
        d[1] = __floats2half2_rn(v.z, v.w);
        return;
    }

    __shared__ __align__(16) float xs[32][EMB];
    __shared__ int toks[32];

    const int g = tid;
    const int rowbase = (blockIdx.x - WCONV_BLOCKS) * 32;

    if (blockIdx.x == WCONV_BLOCKS) {
        // reset all coordination state each replay
        g_sm_role[g] = 0;
        if (g < NCHUNK) g_cnt[g] = 0;
        if (g == 255) { g_marked = 0; g_tile_ctr = 0; g_exit_ctr = 0; }
    }
    if (g < 32) toks[g] = tokens[rowbase + g];

    float4 w4[16];
    float bi = 0.f;
    if (g < G3) {
        const float4* wr = reinterpret_cast<const float4*>(w_ih + g * EMB);
#pragma unroll
        for (int i = 0; i < 16; ++i) w4[i] = wr[i];
        bi = b_ih[g];
    }
    __syncthreads();
    for (int idx = g; idx < 32 * EMB; idx += 256) {
        int r = idx >> 6, c = idx & 63;
        xs[r][c] = emb[(int64_t)toks[r] * EMB + c];
    }
    __syncthreads();

    if (g < G3) {
#pragma unroll 4
        for (int r = 0; r < 32; ++r) {
            const float4* xv = reinterpret_cast<const float4*>(xs[r]);
            float a0 = bi, a1 = 0.f, a2 = 0.f, a3 = 0.f;
#pragma unroll
            for (int i = 0; i < 16; ++i) {
                float4 h4 = xv[i];
                a0 += w4[i].x * h4.x;
                a1 += w4[i].y * h4.y;
                a2 += w4[i].z * h4.z;
                a3 += w4[i].w * h4.w;
            }
            g_xp[(rowbase + r) * G3 + g] = (a0 + a1) + (a2 + a3);
        }
    }
}

// ---------------------------------------------------------------------------
// Fat kernel, grid = 16 + 12000, 256 threads, occ 2:
//   blocks 0..15 : GRU (wave-1 -> distinct SMs). Mark g_sm_role[smid]=1,
//                  then run the 256-step scan, publishing chunk flags.
//   blocks 16..  : ONE GEMM tile each, claimed from an atomic counter.
//                  Blocks landing on a GRU SM exit immediately (budgeted),
//                  keeping GRU SMs exclusive while the scheduler back-fills.
//                  One-tile-per-CTA restores HW CTA-turnover pipelining.
// ---------------------------------------------------------------------------
__global__ __launch_bounds__(256, 2) void fat_kernel(
    const float* __restrict__ w_hh, const float* __restrict__ b_hh,
    const float* __restrict__ bias, float* __restrict__ C)
{
    extern __shared__ __align__(16) char smraw[];
    __shared__ int s_go, s_tile;

    const int tid = threadIdx.x;

    if (blockIdx.x < 16) {
        // ============ GRU role: 256 threads, 4 per h-index ============
        if (tid == 0) {
            atomicExch(&g_sm_role[smid()], 1);
            __threadfence();
            atomicAdd(&g_marked, 1);
        }
        float* hsm = reinterpret_cast<float*>(smraw);    // [2][64]

        const int t  = tid;
        const int p  = t >> 2;        // 0..63
        const int q  = t & 3;
        const int k0 = q * 16;
        const int b  = blockIdx.x;
        const int row0 = b * SEQ;

        unsigned long long wr[8], wz[8], wn[8];
        {
            const unsigned long long* Wr =
                reinterpret_cast<const unsigned long long*>(w_hh + (p      ) * HID + k0);
            const unsigned long long* Wz =
                reinterpret_cast<const unsigned long long*>(w_hh + (p +  64) * HID + k0);
            const unsigned long long* Wn =
                reinterpret_cast<const unsigned long long*>(w_hh + (p + 128) * HID + k0);
#pragma unroll
            for (int i = 0; i < 8; ++i) { wr[i] = Wr[i]; wz[i] = Wz[i]; wn[i] = Wn[i]; }
        }
        const float br = b_hh[p], bz = b_hh[p + 64], bn = b_hh[p + 128];

        if (t < 2 * HID) hsm[t] = 0.f;

        const float* xp0 = g_xp + (size_t)row0 * G3;
        float xr = xp0[p], xz = xp0[p + 64], xn = xp0[p + 128];
        float h_old = 0.f;
        __syncthreads();

        int cur = 0;
#pragma unroll 1
        for (int s = 0; s < SEQ; ++s) {
            float xr_n = 0.f, xz_n = 0.f, xn_n = 0.f;
            if (s + 1 < SEQ) {
                const float* xpn = g_xp + (size_t)(row0 + s + 1) * G3;
                xr_n = xpn[p]; xz_n = xpn[p + 64]; xn_n = xpn[p + 128];
            }

            unsigned long long ar0 = 0, ar1 = 0, az0 = 0, az1 = 0, an0 = 0, an1 = 0;
            const unsigned long long* h2 =
                reinterpret_cast<const unsigned long long*>(hsm + cur * HID + k0);
#pragma unroll
            for (int i = 0; i < 8; i += 2) {
                unsigned long long h0 = h2[i], h1 = h2[i + 1];
                fma2(ar0, wr[i], h0); fma2(ar1, wr[i + 1], h1);
                fma2(az0, wz[i], h0); fma2(az1, wz[i + 1], h1);
                fma2(an0, wn[i], h0); fma2(an1, wn[i + 1], h1);
            }
            float dr = upsum(ar0) + upsum(ar1);
            float dz = upsum(az0) + upsum(az1);
            float dn = upsum(an0) + upsum(an1);
            dr += __shfl_xor_sync(0xffffffffu, dr, 1);
            dz += __shfl_xor_sync(0xffffffffu, dz, 1);
            dn += __shfl_xor_sync(0xffffffffu, dn, 1);
            dr += __shfl_xor_sync(0xffffffffu, dr, 2);
            dz += __shfl_xor_sync(0xffffffffu, dz, 2);
            dn += __shfl_xor_sync(0xffffffffu, dn, 2);

            const float r = fsigm(xr + br + dr);
            const float z = fsigm(xz + bz + dz);
            const float n = ftanh(xn + r * (dn + bn));
            const float hnew = n + z * (h_old - n);

            if (q == 0) {
                hsm[(cur ^ 1) * HID + p] = hnew;
                const int hrow = ((s >> 4) * 16 + b) * 16 + (s & 15);
                g_hh[(size_t)hrow * HID + p] = __float2half_rn(hnew);
            }
            h_old = hnew;
            __syncthreads();
            if ((s & 15) == 15 && t == 0) {
                __threadfence();
                atomicAdd(&g_cnt[s >> 4], 1);
            }
            cur ^= 1;
            xr = xr_n; xz = xz_n; xn = xn_n;
        }
        return;
    }

    // ============ GEMM role: one tile per CTA ============
    if (tid == 0) {
        // wait for all GRU blocks to publish their SM, then role-check
        volatile int* mp = &g_marked;
        while (*mp < 16) __nanosleep(128);
        int go = 1;
        if (g_sm_role[smid()] == 1) {
            if (atomicAdd(&g_exit_ctr, 1) < EXIT_BUDGET) go = 0;
        }
        s_tile = go ? atomicAdd(&g_tile_ctr, 1) : NTILE;
        s_go = go;
    }
    __syncthreads();
    const int tile = s_tile;
    if (!s_go || tile >= NTILE) return;

    __half* As = reinterpret_cast<__half*>(smraw);
    __half* Bs = As + GM * LDS_H;
    const uint32_t As_u = smem_u32(As);
    const uint32_t Bs_u = smem_u32(Bs);

    const int wid  = tid >> 5;
    const int lane = tid & 31;
    const int wm   = wid >> 2;     // 0..1
    const int wn   = wid & 3;      // 0..3

    const int a_row = wm * 64 + ((lane >> 3) & 1) * 8 + (lane & 7);
    const int a_kc  = (lane >> 4) * 16;
    const int b_row = wn * 32 + (lane >> 4) * 8 + (lane & 7);
    const int b_kc  = ((lane >> 3) & 1) * 16;
    const int col_w = wn * 32 + 2 * (lane & 3);

    const int by = tile / TPB, bx = tile % TPB;
    const int nbase = bx * GN;

    // gate on producer chunk
    {
        volatile int* cp = &g_cnt[by >> 1];
        while (*cp < BATCH) __nanosleep(256);
        __threadfence();
    }

    // ---- stage A and B ----
    {
        const uint4* Ag = reinterpret_cast<const uint4*>(g_hh + (size_t)by * GM * HID);
        const uint4* Bg = reinterpret_cast<const uint4*>(g_wh + (size_t)nbase * HID);
#pragma unroll
        for (int i = 0; i < 4; ++i) {
            int idx = tid + i * 256;
            int m = idx >> 3, c = idx & 7;
            *reinterpret_cast<uint4*>(As + m * LDS_H + c * 8) = Ag[idx];
            *reinterpret_cast<uint4*>(Bs + m * LDS_H + c * 8) = Bg[idx];
        }
    }
    __syncthreads();

    // ---- mainloop ----
    float acc[4][4][4];
#pragma unroll
    for (int mt = 0; mt < 4; ++mt)
#pragma unroll
        for (int nt = 0; nt < 4; ++nt)
#pragma unroll
            for (int r = 0; r < 4; ++r) acc[mt][nt][r] = 0.f;

#pragma unroll
    for (int ks = 0; ks < 4; ++ks) {
        uint32_t a[4][4], bfr[2][4];
#pragma unroll
        for (int mt = 0; mt < 4; ++mt)
            ldsm_x4(a[mt], As_u + (uint32_t)((a_row + mt * 16) * 144 + ks * 32 + a_kc));
#pragma unroll
        for (int p2 = 0; p2 < 2; ++p2)
            ldsm_x4(bfr[p2], Bs_u + (uint32_t)((b_row + p2 * 16) * 144 + ks * 32 + b_kc));
#pragma unroll
        for (int mt = 0; mt < 4; ++mt)
#pragma unroll
            for (int nt = 0; nt < 4; ++nt)
                mma16816(acc[mt][nt], a[mt], &bfr[nt >> 1][(nt & 1) * 2]);
    }

    // ---- epilogue: bias add + direct float2 stores (row-permuted C) ----
    const int col_l = nbase + col_w;
    float2 bv[4];
#pragma unroll
    for (int nt = 0; nt < 4; ++nt)
        bv[nt] = *reinterpret_cast<const float2*>(bias + col_l + nt * 8);

    const int Rbase = by * GM + wm * 64 + (lane >> 2);
#pragma unroll
    for (int mt = 0; mt < 4; ++mt) {
        const size_t r0 = (size_t)crow(Rbase + mt * 16)     * VOCAB;
        const size_t r1 = (size_t)crow(Rbase + mt * 16 + 8) * VOCAB;
#pragma unroll
        for (int nt = 0; nt < 4; ++nt) {
            float2 v0 = make_float2(acc[mt][nt][0] + bv[nt].x,
                                    acc[mt][nt][1] + bv[nt].y);
            float2 v1 = make_float2(acc[mt][nt][2] + bv[nt].x,
                                    acc[mt][nt][3] + bv[nt].y);
            *reinterpret_cast<float2*>(C + r0 + col_l + nt * 8) = v0;
            *reinterpret_cast<float2*>(C + r1 + col_l + nt * 8) = v1;
        }
    }
}

// ---------------------------------------------------------------------------
// Launch
// Inputs: 0 tokens(int32) 1 emb 2 w_ih 3 w_hh 4 b_ih 5 b_hh 6 w_out 7 b_out
// ---------------------------------------------------------------------------
extern "C" void kernel_launch(void* const* d_in, const int* in_sizes, int n_in,
                              void* d_out, int out_size)
{
    const int*   tokens = (const int*)  d_in[0];
    const float* emb    = (const float*)d_in[1];
    const float* w_ih   = (const float*)d_in[2];
    const float* w_hh   = (const float*)d_in[3];
    const float* b_ih   = (const float*)d_in[4];
    const float* b_hh   = (const float*)d_in[5];
    const float* w_out  = (const float*)d_in[6];
    const float* b_out  = (const float*)d_in[7];
    float* out = (float*)d_out;

    (void)in_sizes; (void)n_in; (void)out_size;

    cudaFuncSetAttribute(fat_kernel,
                         cudaFuncAttributeMaxDynamicSharedMemorySize, TILE_SM);

    prep_kernel<<<WCONV_BLOCKS + ROWS / 32, 256>>>(w_out, tokens, emb, w_ih, b_ih);
    fat_kernel<<<GRID_FAT, 256, TILE_SM>>>(w_hh, b_hh, b_out, out);
}

// round 14
// speedup vs baseline: 1.0741x; 1.0741x over previous
#include <cuda_runtime.h>
#include <cuda_fp16.h>
#include <cstdint>

// Problem constants
#define VOCAB 32000
#define EMB   64
#define HID   64
#define BATCH 16
#define SEQ   256
#define ROWS  (BATCH*SEQ)   // 4096
#define G3    (3*HID)       // 192
#define NCHUNK 16           // 16 chunks of 16 steps
#define WCONV_BLOCKS 2000   // 512000 float4 / 256

// GEMM tiling (R3-proven shape)
#define GM 128
#define GN 128
#define LDS_H 72                                   // halves per smem row (64+8 pad)
#define TILE_SM (GM * LDS_H * 2 + GN * LDS_H * 2)  // 36864 B
#define NTILE ((VOCAB / GN) * (ROWS / GM))   // 250*32 = 8000
#define TPB   (VOCAB / GN)                   // 250

// Launch shape: 16 GRU blocks + oversubscribed one-tile GEMM blocks
#define GEMM_GRID   12000
#define GRID_FAT    (16 + GEMM_GRID)
#define EXIT_BUDGET 3500     // guaranteed workers: 12000-3500 = 8500 > 8000

// GRU prefetch depth (steps of xp staged ahead in registers)
#define PFD 4

// Scratch (device globals; no allocation allowed)
__device__ float  g_xp[ROWS * G3];          // x @ w_ih^T + b_ih
__device__ __half g_hh[ROWS * HID];         // h, layout [chunk][batch][s%16][64]
__device__ __half g_wh[VOCAB * HID];        // w_out fp16
__device__ int    g_cnt[NCHUNK];            // chunk completion counters
__device__ int    g_sm_role[256];           // 1 = GRU owns this SM
__device__ int    g_marked;                 // # GRU blocks that published role
__device__ int    g_tile_ctr;               // GEMM tile claim counter
__device__ int    g_exit_ctr;               // churn budget counter

// ---------------------------------------------------------------------------
// helpers
// ---------------------------------------------------------------------------
__device__ __forceinline__ void fma2(unsigned long long& d,
                                     unsigned long long a, unsigned long long b) {
    asm("fma.rn.f32x2 %0, %1, %2, %0;" : "+l"(d) : "l"(a), "l"(b));
}
__device__ __forceinline__ float upsum(unsigned long long v) {
    unsigned lo, hi;
    asm("mov.b64 {%0,%1}, %2;" : "=r"(lo), "=r"(hi) : "l"(v));
    return __uint_as_float(lo) + __uint_as_float(hi);
}
__device__ __forceinline__ float frcp(float x) {
    float r; asm("rcp.approx.f32 %0, %1;" : "=f"(r) : "f"(x)); return r;
}
__device__ __forceinline__ float fsigm(float x) { return frcp(1.f + __expf(-x)); }
__device__ __forceinline__ float ftanh(float x) {
    return 1.f - 2.f * frcp(__expf(2.f * x) + 1.f);
}
__device__ __forceinline__ void ldsm_x4(uint32_t* r, uint32_t addr) {
    asm volatile("ldmatrix.sync.aligned.m8n8.x4.shared.b16 {%0,%1,%2,%3}, [%4];"
                 : "=r"(r[0]), "=r"(r[1]), "=r"(r[2]), "=r"(r[3]) : "r"(addr));
}
__device__ __forceinline__ void mma16816(float* d, const uint32_t* a, const uint32_t* b) {
    asm volatile(
        "mma.sync.aligned.m16n8k16.row.col.f32.f16.f16.f32 "
        "{%0,%1,%2,%3},{%4,%5,%6,%7},{%8,%9},{%0,%1,%2,%3};"
        : "+f"(d[0]), "+f"(d[1]), "+f"(d[2]), "+f"(d[3])
        : "r"(a[0]), "r"(a[1]), "r"(a[2]), "r"(a[3]), "r"(b[0]), "r"(b[1]));
}
__device__ __forceinline__ uint32_t smem_u32(const void* p) {
    uint32_t a;
    asm("{ .reg .u64 t; cvta.to.shared.u64 t, %1; cvt.u32.u64 %0, t; }"
        : "=r"(a) : "l"(p));
    return a;
}
__device__ __forceinline__ int smid() {
    int s; asm("mov.u32 %0, %%smid;" : "=r"(s)); return s;
}
// g_hh row R -> original (b,s) C row:  b = (R>>4)&15, s = (R>>8)*16 + (R&15)
__device__ __forceinline__ int crow(int R) {
    return (((R >> 4) & 15) << 8) + ((R >> 8) << 4) + (R & 15);
}

// ---------------------------------------------------------------------------
// Prep kernel: blocks [0,2000) convert w_out fp32->fp16;
// blocks [2000, 2128) embedding + input projection (+ counter resets).
// ---------------------------------------------------------------------------
__global__ __launch_bounds__(256) void prep_kernel(
    const float* __restrict__ W,
    const int* __restrict__ tokens, const float* __restrict__ emb,
    const float* __restrict__ w_ih, const float* __restrict__ b_ih)
{
    const int tid = threadIdx.x;

    if (blockIdx.x < WCONV_BLOCKS) {
        size_t i = (size_t)blockIdx.x * 256 + tid;
        float4 v = reinterpret_cast<const float4*>(W)[i];
        __half2* d = reinterpret_cast<__half2*>(g_wh + i * 4);
        d[0] = __floats2half2_rn(v.x, v.y);
        d[1] = __floats2half2_rn(v.z, v.w);
        return;
    }

    __shared__ __align__(16) float xs[32][EMB];
    __shared__ int toks[32];

    const int g = tid;
    const int rowbase = (blockIdx.x - WCONV_BLOCKS) * 32;

    if (blockIdx.x == WCONV_BLOCKS) {
        // reset all coordination state each replay
        g_sm_role[g] = 0;
        if (g < NCHUNK) g_cnt[g] = 0;
        if (g == 255) { g_marked = 0; g_tile_ctr = 0; g_exit_ctr = 0; }
    }
    if (g < 32) toks[g] = tokens[rowbase + g];

    float4 w4[16];
    float bi = 0.f;
    if (g < G3) {
        const float4* wr = reinterpret_cast<const float4*>(w_ih + g * EMB);
#pragma unroll
        for (int i = 0; i < 16; ++i) w4[i] = wr[i];
        bi = b_ih[g];
    }
    __syncthreads();
    for (int idx = g; idx < 32 * EMB; idx += 256) {
        int r = idx >> 6, c = idx & 63;
        xs[r][c] = emb[(int64_t)toks[r] * EMB + c];
    }
    __syncthreads();

    if (g < G3) {
#pragma unroll 4
        for (int r = 0; r < 32; ++r) {
            const float4* xv = reinterpret_cast<const float4*>(xs[r]);
            float a0 = bi, a1 = 0.f, a2 = 0.f, a3 = 0.f;
#pragma unroll
            for (int i = 0; i < 16; ++i) {
                float4 h4 = xv[i];
                a0 += w4[i].x * h4.x;
                a1 += w4[i].y * h4.y;
                a2 += w4[i].z * h4.z;
                a3 += w4[i].w * h4.w;
            }
            g_xp[(rowbase + r) * G3 + g] = (a0 + a1) + (a2 + a3);
        }
    }
}

// ---------------------------------------------------------------------------
// Fat kernel, grid = 16 + 12000, 256 threads, occ 2:
//   blocks 0..15 : GRU (wave-1 -> distinct SMs), depth-4 register prefetch of
//                  xp so the serial chain never waits on loaded-DRAM latency.
//   blocks 16..  : ONE GEMM tile each from an atomic counter; blocks landing
//                  on a GRU SM exit (budgeted) to keep those SMs exclusive.
// ---------------------------------------------------------------------------
__global__ __launch_bounds__(256, 2) void fat_kernel(
    const float* __restrict__ w_hh, const float* __restrict__ b_hh,
    const float* __restrict__ bias, float* __restrict__ C)
{
    extern __shared__ __align__(16) char smraw[];
    __shared__ int s_go, s_tile;

    const int tid = threadIdx.x;

    if (blockIdx.x < 16) {
        // ============ GRU role: 256 threads, 4 per h-index ============
        if (tid == 0) {
            atomicExch(&g_sm_role[smid()], 1);
            __threadfence();
            atomicAdd(&g_marked, 1);
        }
        float* hsm = reinterpret_cast<float*>(smraw);    // [2][64]

        const int t  = tid;
        const int p  = t >> 2;        // 0..63
        const int q  = t & 3;
        const int k0 = q * 16;
        const int b  = blockIdx.x;
        const int row0 = b * SEQ;

        unsigned long long wr[8], wz[8], wn[8];
        {
            const unsigned long long* Wr =
                reinterpret_cast<const unsigned long long*>(w_hh + (p      ) * HID + k0);
            const unsigned long long* Wz =
                reinterpret_cast<const unsigned long long*>(w_hh + (p +  64) * HID + k0);
            const unsigned long long* Wn =
                reinterpret_cast<const unsigned long long*>(w_hh + (p + 128) * HID + k0);
#pragma unroll
            for (int i = 0; i < 8; ++i) { wr[i] = Wr[i]; wz[i] = Wz[i]; wn[i] = Wn[i]; }
        }
        const float br = b_hh[p], bz = b_hh[p + 64], bn = b_hh[p + 128];

        if (t < 2 * HID) hsm[t] = 0.f;

        // depth-PFD register prefetch ring for xp
        float pr[PFD], pz[PFD], pn[PFD];
#pragma unroll
        for (int j = 0; j < PFD; ++j) {
            const float* x = g_xp + (size_t)(row0 + j) * G3;
            pr[j] = x[p]; pz[j] = x[p + 64]; pn[j] = x[p + 128];
        }
        float h_old = 0.f;
        __syncthreads();

        int cur = 0;
#pragma unroll 1
        for (int s4 = 0; s4 < SEQ / PFD; ++s4) {
#pragma unroll
            for (int j = 0; j < PFD; ++j) {
                const int s = s4 * PFD + j;

                // consume slot j, immediately refill for step s+PFD
                const float xr = pr[j], xz = pz[j], xn = pn[j];
                if (s + PFD < SEQ) {
                    const float* xpn = g_xp + (size_t)(row0 + s + PFD) * G3;
                    pr[j] = xpn[p]; pz[j] = xpn[p + 64]; pn[j] = xpn[p + 128];
                }

                unsigned long long ar0 = 0, ar1 = 0, az0 = 0, az1 = 0, an0 = 0, an1 = 0;
                const unsigned long long* h2 =
                    reinterpret_cast<const unsigned long long*>(hsm + cur * HID + k0);
#pragma unroll
                for (int i = 0; i < 8; i += 2) {
                    unsigned long long h0 = h2[i], h1 = h2[i + 1];
                    fma2(ar0, wr[i], h0); fma2(ar1, wr[i + 1], h1);
                    fma2(az0, wz[i], h0); fma2(az1, wz[i + 1], h1);
                    fma2(an0, wn[i], h0); fma2(an1, wn[i + 1], h1);
                }
                float dr = upsum(ar0) + upsum(ar1);
                float dz = upsum(az0) + upsum(az1);
                float dn = upsum(an0) + upsum(an1);
                dr += __shfl_xor_sync(0xffffffffu, dr, 1);
                dz += __shfl_xor_sync(0xffffffffu, dz, 1);
                dn += __shfl_xor_sync(0xffffffffu, dn, 1);
                dr += __shfl_xor_sync(0xffffffffu, dr, 2);
                dz += __shfl_xor_sync(0xffffffffu, dz, 2);
                dn += __shfl_xor_sync(0xffffffffu, dn, 2);

                const float r = fsigm(xr + br + dr);
                const float z = fsigm(xz + bz + dz);
                const float n = ftanh(xn + r * (dn + bn));
                const float hnew = n + z * (h_old - n);

                if (q == 0) {
                    hsm[(cur ^ 1) * HID + p] = hnew;
                    const int hrow = ((s >> 4) * 16 + b) * 16 + (s & 15);
                    g_hh[(size_t)hrow * HID + p] = __float2half_rn(hnew);
                }
                h_old = hnew;
                __syncthreads();
                if ((s & 15) == 15 && t == 0) {
                    __threadfence();
                    atomicAdd(&g_cnt[s >> 4], 1);
                }
                cur ^= 1;
            }
        }
        return;
    }

    // ============ GEMM role: one tile per CTA ============
    if (tid == 0) {
        // wait for all GRU blocks to publish their SM, then role-check
        volatile int* mp = &g_marked;
        while (*mp < 16) __nanosleep(128);
        int go = 1;
        if (g_sm_role[smid()] == 1) {
            if (atomicAdd(&g_exit_ctr, 1) < EXIT_BUDGET) go = 0;
        }
        s_tile = go ? atomicAdd(&g_tile_ctr, 1) : NTILE;
        s_go = go;
    }
    __syncthreads();
    const int tile = s_tile;
    if (!s_go || tile >= NTILE) return;

    __half* As = reinterpret_cast<__half*>(smraw);
    __half* Bs = As + GM * LDS_H;
    const uint32_t As_u = smem_u32(As);
    const uint32_t Bs_u = smem_u32(Bs);

    const int wid  = tid >> 5;
    const int lane = tid & 31;
    const int wm   = wid >> 2;     // 0..1
    const int wn   = wid & 3;      // 0..3

    const int a_row = wm * 64 + ((lane >> 3) & 1) * 8 + (lane & 7);
    const int a_kc  = (lane >> 4) * 16;
    const int b_row = wn * 32 + (lane >> 4) * 8 + (lane & 7);
    const int b_kc  = ((lane >> 3) & 1) * 16;
    const int col_w = wn * 32 + 2 * (lane & 3);

    const int by = tile / TPB, bx = tile % TPB;
    const int nbase = bx * GN;

    // gate on producer chunk
    {
        volatile int* cp = &g_cnt[by >> 1];
        while (*cp < BATCH) __nanosleep(256);
        __threadfence();
    }

    // ---- stage A and B ----
    {
        const uint4* Ag = reinterpret_cast<const uint4*>(g_hh + (size_t)by * GM * HID);
        const uint4* Bg = reinterpret_cast<const uint4*>(g_wh + (size_t)nbase * HID);
#pragma unroll
        for (int i = 0; i < 4; ++i) {
            int idx = tid + i * 256;
            int m = idx >> 3, c = idx & 7;
            *reinterpret_cast<uint4*>(As + m * LDS_H + c * 8) = Ag[idx];
            *reinterpret_cast<uint4*>(Bs + m * LDS_H + c * 8) = Bg[idx];
        }
    }
    __syncthreads();

    // ---- mainloop ----
    float acc[4][4][4];
#pragma unroll
    for (int mt = 0; mt < 4; ++mt)
#pragma unroll
        for (int nt = 0; nt < 4; ++nt)
#pragma unroll
            for (int r = 0; r < 4; ++r) acc[mt][nt][r] = 0.f;

#pragma unroll
    for (int ks = 0; ks < 4; ++ks) {
        uint32_t a[4][4], bfr[2][4];
#pragma unroll
        for (int mt = 0; mt < 4; ++mt)
            ldsm_x4(a[mt], As_u + (uint32_t)((a_row + mt * 16) * 144 + ks * 32 + a_kc));
#pragma unroll
        for (int p2 = 0; p2 < 2; ++p2)
            ldsm_x4(bfr[p2], Bs_u + (uint32_t)((b_row + p2 * 16) * 144 + ks * 32 + b_kc));
#pragma unroll
        for (int mt = 0; mt < 4; ++mt)
#pragma unroll
            for (int nt = 0; nt < 4; ++nt)
                mma16816(acc[mt][nt], a[mt], &bfr[nt >> 1][(nt & 1) * 2]);
    }

    // ---- epilogue: bias add + direct float2 stores (row-permuted C) ----
    const int col_l = nbase + col_w;
    float2 bv[4];
#pragma unroll
    for (int nt = 0; nt < 4; ++nt)
        bv[nt] = *reinterpret_cast<const float2*>(bias + col_l + nt * 8);

    const int Rbase = by * GM + wm * 64 + (lane >> 2);
#pragma unroll
    for (int mt = 0; mt < 4; ++mt) {
        const size_t r0 = (size_t)crow(Rbase + mt * 16)     * VOCAB;
        const size_t r1 = (size_t)crow(Rbase + mt * 16 + 8) * VOCAB;
#pragma unroll
        for (int nt = 0; nt < 4; ++nt) {
            float2 v0 = make_float2(acc[mt][nt][0] + bv[nt].x,
                                    acc[mt][nt][1] + bv[nt].y);
            float2 v1 = make_float2(acc[mt][nt][2] + bv[nt].x,
                                    acc[mt][nt][3] + bv[nt].y);
            *reinterpret_cast<float2*>(C + r0 + col_l + nt * 8) = v0;
            *reinterpret_cast<float2*>(C + r1 + col_l + nt * 8) = v1;
        }
    }
}

// ---------------------------------------------------------------------------
// Launch
// Inputs: 0 tokens(int32) 1 emb 2 w_ih 3 w_hh 4 b_ih 5 b_hh 6 w_out 7 b_out
// ---------------------------------------------------------------------------
extern "C" void kernel_launch(void* const* d_in, const int* in_sizes, int n_in,
                              void* d_out, int out_size)
{
    const int*   tokens = (const int*)  d_in[0];
    const float* emb    = (const float*)d_in[1];
    const float* w_ih   = (const float*)d_in[2];
    const float* w_hh   = (const float*)d_in[3];
    const float* b_ih   = (const float*)d_in[4];
    const float* b_hh   = (const float*)d_in[5];
    const float* w_out  = (const float*)d_in[6];
    const float* b_out  = (const float*)d_in[7];
    float* out = (float*)d_out;

    (void)in_sizes; (void)n_in; (void)out_size;

    cudaFuncSetAttribute(fat_kernel,
                         cudaFuncAttributeMaxDynamicSharedMemorySize, TILE_SM);

    prep_kernel<<<WCONV_BLOCKS + ROWS / 32, 256>>>(w_out, tokens, emb, w_ih, b_ih);
    fat_kernel<<<GRID_FAT, 256, TILE_SM>>>(w_hh, b_hh, b_out, out);
}

// round 15
// speedup vs baseline: 1.0797x; 1.0052x over previous
#include <cuda_runtime.h>
#include <cuda_fp16.h>
#include <cstdint>

// Problem constants
#define VOCAB 32000
#define EMB   64
#define HID   64
#define BATCH 16
#define SEQ   256
#define ROWS  (BATCH*SEQ)   // 4096
#define G3    (3*HID)       // 192
#define NCHUNK 16           // 16 chunks of 16 steps
#define WCONV_BLOCKS 2000   // 512000 float4 / 256

// GEMM tiling (R3-proven shape)
#define GM 128
#define GN 128
#define LDS_H 72                                   // halves per smem row (64+8 pad)
#define TILE_SM (GM * LDS_H * 2 + GN * LDS_H * 2)  // 36864 B
#define NTILE ((VOCAB / GN) * (ROWS / GM))   // 250*32 = 8000
#define TPB   (VOCAB / GN)                   // 250

// Launch shape: 16 GRU blocks + oversubscribed one-tile GEMM blocks
#define GEMM_GRID   12000
#define GRID_FAT    (16 + GEMM_GRID)
#define EXIT_BUDGET 3500     // guaranteed workers: 12000-3500 = 8500 > 8000

// GRU xp chunk staging: 16 steps * 192 floats = 12288 B per buffer
#define XCHUNK_B 12288
#define XCHUNK_F 3072

// Scratch (device globals; no allocation allowed)
__device__ float  g_xp[ROWS * G3];          // x @ w_ih^T + b_ih
__device__ __half g_hh[ROWS * HID];         // h, layout [chunk][batch][s%16][64]
__device__ __half g_wh[VOCAB * HID];        // w_out fp16
__device__ int    g_cnt[NCHUNK];            // chunk completion counters
__device__ int    g_sm_role[256];           // 1 = GRU owns this SM
__device__ int    g_marked;                 // # GRU blocks that published role
__device__ int    g_tile_ctr;               // GEMM tile claim counter
__device__ int    g_exit_ctr;               // churn budget counter

// ---------------------------------------------------------------------------
// helpers
// ---------------------------------------------------------------------------
__device__ __forceinline__ void fma2(unsigned long long& d,
                                     unsigned long long a, unsigned long long b) {
    asm("fma.rn.f32x2 %0, %1, %2, %0;" : "+l"(d) : "l"(a), "l"(b));
}
__device__ __forceinline__ float upsum(unsigned long long v) {
    unsigned lo, hi;
    asm("mov.b64 {%0,%1}, %2;" : "=r"(lo), "=r"(hi) : "l"(v));
    return __uint_as_float(lo) + __uint_as_float(hi);
}
__device__ __forceinline__ float frcp(float x) {
    float r; asm("rcp.approx.f32 %0, %1;" : "=f"(r) : "f"(x)); return r;
}
__device__ __forceinline__ float fsigm(float x) { return frcp(1.f + __expf(-x)); }
__device__ __forceinline__ float ftanh(float x) {
    return 1.f - 2.f * frcp(__expf(2.f * x) + 1.f);
}
__device__ __forceinline__ void cp16(uint32_t dst, const void* src) {
    asm volatile("cp.async.ca.shared.global [%0], [%1], 16;"
                 :: "r"(dst), "l"(src) : "memory");
}
__device__ __forceinline__ void cp_commit() {
    asm volatile("cp.async.commit_group;" ::: "memory");
}
__device__ __forceinline__ void ldsm_x4(uint32_t* r, uint32_t addr) {
    asm volatile("ldmatrix.sync.aligned.m8n8.x4.shared.b16 {%0,%1,%2,%3}, [%4];"
                 : "=r"(r[0]), "=r"(r[1]), "=r"(r[2]), "=r"(r[3]) : "r"(addr));
}
__device__ __forceinline__ void mma16816(float* d, const uint32_t* a, const uint32_t* b) {
    asm volatile(
        "mma.sync.aligned.m16n8k16.row.col.f32.f16.f16.f32 "
        "{%0,%1,%2,%3},{%4,%5,%6,%7},{%8,%9},{%0,%1,%2,%3};"
        : "+f"(d[0]), "+f"(d[1]), "+f"(d[2]), "+f"(d[3])
        : "r"(a[0]), "r"(a[1]), "r"(a[2]), "r"(a[3]), "r"(b[0]), "r"(b[1]));
}
__device__ __forceinline__ uint32_t smem_u32(const void* p) {
    uint32_t a;
    asm("{ .reg .u64 t; cvta.to.shared.u64 t, %1; cvt.u32.u64 %0, t; }"
        : "=r"(a) : "l"(p));
    return a;
}
__device__ __forceinline__ int smid() {
    int s; asm("mov.u32 %0, %%smid;" : "=r"(s)); return s;
}
// g_hh row R -> original (b,s) C row:  b = (R>>4)&15, s = (R>>8)*16 + (R&15)
__device__ __forceinline__ int crow(int R) {
    return (((R >> 4) & 15) << 8) + ((R >> 8) << 4) + (R & 15);
}

// ---------------------------------------------------------------------------
// Prep kernel: blocks [0,2000) convert w_out fp32->fp16;
// blocks [2000, 2128) embedding + input projection (+ counter resets).
// ---------------------------------------------------------------------------
__global__ __launch_bounds__(256) void prep_kernel(
    const float* __restrict__ W,
    const int* __restrict__ tokens, const float* __restrict__ emb,
    const float* __restrict__ w_ih, const float* __restrict__ b_ih)
{
    const int tid = threadIdx.x;

    if (blockIdx.x < WCONV_BLOCKS) {
        size_t i = (size_t)blockIdx.x * 256 + tid;
        float4 v = reinterpret_cast<const float4*>(W)[i];
        __half2* d = reinterpret_cast<__half2*>(g_wh + i * 4);
        d[0] = __floats2half2_rn(v.x, v.y);
        d[1] = __floats2half2_rn(v.z, v.w);
        return;
    }

    __shared__ __align__(16) float xs[32][EMB];
    __shared__ int toks[32];

    const int g = tid;
    const int rowbase = (blockIdx.x - WCONV_BLOCKS) * 32;

    if (blockIdx.x == WCONV_BLOCKS) {
        // reset all coordination state each replay
        g_sm_role[g] = 0;
        if (g < NCHUNK) g_cnt[g] = 0;
        if (g == 255) { g_marked = 0; g_tile_ctr = 0; g_exit_ctr = 0; }
    }
    if (g < 32) toks[g] = tokens[rowbase + g];

    float4 w4[16];
    float bi = 0.f;
    if (g < G3) {
        const float4* wr = reinterpret_cast<const float4*>(w_ih + g * EMB);
#pragma unroll
        for (int i = 0; i < 16; ++i) w4[i] = wr[i];
        bi = b_ih[g];
    }
    __syncthreads();
    for (int idx = g; idx < 32 * EMB; idx += 256) {
        int r = idx >> 6, c = idx & 63;
        xs[r][c] = emb[(int64_t)toks[r] * EMB + c];
    }
    __syncthreads();

    if (g < G3) {
#pragma unroll 4
        for (int r = 0; r < 32; ++r) {
            const float4* xv = reinterpret_cast<const float4*>(xs[r]);
            float a0 = bi, a1 = 0.f, a2 = 0.f, a3 = 0.f;
#pragma unroll
            for (int i = 0; i < 16; ++i) {
                float4 h4 = xv[i];
                a0 += w4[i].x * h4.x;
                a1 += w4[i].y * h4.y;
                a2 += w4[i].z * h4.z;
                a3 += w4[i].w * h4.w;
            }
            g_xp[(rowbase + r) * G3 + g] = (a0 + a1) + (a2 + a3);
        }
    }
}

// ---------------------------------------------------------------------------
// Fat kernel, grid = 16 + 12000, 256 threads, occ 2:
//   blocks 0..15 : GRU (wave-1 -> distinct SMs). xp is staged one 16-step
//                  chunk ahead into a SMEM double-buffer via cp.async
//                  (register-free, 16-step latency slack) so the serial
//                  chain never touches global memory.
//   blocks 16..  : ONE GEMM tile each from an atomic counter; blocks landing
//                  on a GRU SM exit (budgeted) to keep those SMs exclusive.
// ---------------------------------------------------------------------------
__global__ __launch_bounds__(256, 2) void fat_kernel(
    const float* __restrict__ w_hh, const float* __restrict__ b_hh,
    const float* __restrict__ bias, float* __restrict__ C)
{
    extern __shared__ __align__(16) char smraw[];
    __shared__ int s_go, s_tile;

    const int tid = threadIdx.x;

    if (blockIdx.x < 16) {
        // ============ GRU role: 256 threads, 4 per h-index ============
        if (tid == 0) {
            atomicExch(&g_sm_role[smid()], 1);
            __threadfence();
            atomicAdd(&g_marked, 1);
        }
        float* hsm  = reinterpret_cast<float*>(smraw);          // [2][64]
        float* xbuf = reinterpret_cast<float*>(smraw + 512);    // [2][3072]
        const uint32_t xbuf_u = smem_u32(xbuf);

        const int t  = tid;
        const int p  = t >> 2;        // 0..63
        const int q  = t & 3;
        const int k0 = q * 16;
        const int b  = blockIdx.x;
        const int row0 = b * SEQ;

        unsigned long long wr[8], wz[8], wn[8];
        {
            const unsigned long long* Wr =
                reinterpret_cast<const unsigned long long*>(w_hh + (p      ) * HID + k0);
            const unsigned long long* Wz =
                reinterpret_cast<const unsigned long long*>(w_hh + (p +  64) * HID + k0);
            const unsigned long long* Wn =
                reinterpret_cast<const unsigned long long*>(w_hh + (p + 128) * HID + k0);
#pragma unroll
            for (int i = 0; i < 8; ++i) { wr[i] = Wr[i]; wz[i] = Wz[i]; wn[i] = Wn[i]; }
        }
        const float br = b_hh[p], bz = b_hh[p + 64], bn = b_hh[p + 128];

        if (t < 2 * HID) hsm[t] = 0.f;

        // prologue: issue chunk 0 into buffer 0 (cp.async, register-free)
        const char* xsrc = reinterpret_cast<const char*>(g_xp + (size_t)row0 * G3);
        {
#pragma unroll
            for (int i = 0; i < 3; ++i) {
                const int line = tid + i * 256;
                cp16(xbuf_u + line * 16, xsrc + line * 16);
            }
            cp_commit();
        }

        float h_old = 0.f;
        int cur = 0;

#pragma unroll 1
        for (int c = 0; c < NCHUNK; ++c) {
            // issue chunk c+1 into the other buffer, then wait for chunk c
            if (c + 1 < NCHUNK) {
                const char* src = xsrc + (size_t)(c + 1) * XCHUNK_B;
                const uint32_t dst = xbuf_u + ((c + 1) & 1) * XCHUNK_B;
#pragma unroll
                for (int i = 0; i < 3; ++i) {
                    const int line = tid + i * 256;
                    cp16(dst + line * 16, src + line * 16);
                }
                cp_commit();
                asm volatile("cp.async.wait_group 1;" ::: "memory");
            } else {
                asm volatile("cp.async.wait_group 0;" ::: "memory");
            }
            __syncthreads();   // chunk c visible block-wide (also orders hsm init)

            const float* xc = xbuf + (c & 1) * XCHUNK_F;

#pragma unroll 1
            for (int sl = 0; sl < 16; ++sl) {
                const int s = c * 16 + sl;
                const float* xrow = xc + sl * G3;
                const float xr = xrow[p], xz = xrow[p + 64], xn = xrow[p + 128];

                unsigned long long ar0 = 0, ar1 = 0, az0 = 0, az1 = 0, an0 = 0, an1 = 0;
                const unsigned long long* h2 =
                    reinterpret_cast<const unsigned long long*>(hsm + cur * HID + k0);
#pragma unroll
                for (int i = 0; i < 8; i += 2) {
                    unsigned long long h0 = h2[i], h1 = h2[i + 1];
                    fma2(ar0, wr[i], h0); fma2(ar1, wr[i + 1], h1);
                    fma2(az0, wz[i], h0); fma2(az1, wz[i + 1], h1);
                    fma2(an0, wn[i], h0); fma2(an1, wn[i + 1], h1);
                }
                float dr = upsum(ar0) + upsum(ar1);
                float dz = upsum(az0) + upsum(az1);
                float dn = upsum(an0) + upsum(an1);
                dr += __shfl_xor_sync(0xffffffffu, dr, 1);
                dz += __shfl_xor_sync(0xffffffffu, dz, 1);
                dn += __shfl_xor_sync(0xffffffffu, dn, 1);
                dr += __shfl_xor_sync(0xffffffffu, dr, 2);
                dz += __shfl_xor_sync(0xffffffffu, dz, 2);
                dn += __shfl_xor_sync(0xffffffffu, dn, 2);

                const float r = fsigm(xr + br + dr);
                const float z = fsigm(xz + bz + dz);
                const float n = ftanh(xn + r * (dn + bn));
                const float hnew = n + z * (h_old - n);

                if (q == 0) {
                    hsm[(cur ^ 1) * HID + p] = hnew;
                    const int hrow = (c * 16 + b) * 16 + sl;   // [chunk][b][s%16]
                    g_hh[(size_t)hrow * HID + p] = __float2half_rn(hnew);
                }
                h_old = hnew;
                __syncthreads();
                cur ^= 1;
                (void)s;
            }

            if (t == 0) {
                __threadfence();
                atomicAdd(&g_cnt[c], 1);
            }
        }
        return;
    }

    // ============ GEMM role: one tile per CTA ============
    if (tid == 0) {
        // wait for all GRU blocks to publish their SM, then role-check
        volatile int* mp = &g_marked;
        while (*mp < 16) __nanosleep(128);
        int go = 1;
        if (g_sm_role[smid()] == 1) {
            if (atomicAdd(&g_exit_ctr, 1) < EXIT_BUDGET) go = 0;
        }
        s_tile = go ? atomicAdd(&g_tile_ctr, 1) : NTILE;
        s_go = go;
    }
    __syncthreads();
    const int tile = s_tile;
    if (!s_go || tile >= NTILE) return;

    __half* As = reinterpret_cast<__half*>(smraw);
    __half* Bs = As + GM * LDS_H;
    const uint32_t As_u = smem_u32(As);
    const uint32_t Bs_u = smem_u32(Bs);

    const int wid  = tid >> 5;
    const int lane = tid & 31;
    const int wm   = wid >> 2;     // 0..1
    const int wn   = wid & 3;      // 0..3

    const int a_row = wm * 64 + ((lane >> 3) & 1) * 8 + (lane & 7);
    const int a_kc  = (lane >> 4) * 16;
    const int b_row = wn * 32 + (lane >> 4) * 8 + (lane & 7);
    const int b_kc  = ((lane >> 3) & 1) * 16;
    const int col_w = wn * 32 + 2 * (lane & 3);

    const int by = tile / TPB, bx = tile % TPB;
    const int nbase = bx * GN;

    // gate on producer chunk
    {
        volatile int* cp = &g_cnt[by >> 1];
        while (*cp < BATCH) __nanosleep(256);
        __threadfence();
    }

    // ---- stage A and B ----
    {
        const uint4* Ag = reinterpret_cast<const uint4*>(g_hh + (size_t)by * GM * HID);
        const uint4* Bg = reinterpret_cast<const uint4*>(g_wh + (size_t)nbase * HID);
#pragma unroll
        for (int i = 0; i < 4; ++i) {
            int idx = tid + i * 256;
            int m = idx >> 3, c = idx & 7;
            *reinterpret_cast<uint4*>(As + m * LDS_H + c * 8) = Ag[idx];
            *reinterpret_cast<uint4*>(Bs + m * LDS_H + c * 8) = Bg[idx];
        }
    }
    __syncthreads();

    // ---- mainloop ----
    float acc[4][4][4];
#pragma unroll
    for (int mt = 0; mt < 4; ++mt)
#pragma unroll
        for (int nt = 0; nt < 4; ++nt)
#pragma unroll
            for (int r = 0; r < 4; ++r) acc[mt][nt][r] = 0.f;

#pragma unroll
    for (int ks = 0; ks < 4; ++ks) {
        uint32_t a[4][4], bfr[2][4];
#pragma unroll
        for (int mt = 0; mt < 4; ++mt)
            ldsm_x4(a[mt], As_u + (uint32_t)((a_row + mt * 16) * 144 + ks * 32 + a_kc));
#pragma unroll
        for (int p2 = 0; p2 < 2; ++p2)
            ldsm_x4(bfr[p2], Bs_u + (uint32_t)((b_row + p2 * 16) * 144 + ks * 32 + b_kc));
#pragma unroll
        for (int mt = 0; mt < 4; ++mt)
#pragma unroll
            for (int nt = 0; nt < 4; ++nt)
                mma16816(acc[mt][nt], a[mt], &bfr[nt >> 1][(nt & 1) * 2]);
    }

    // ---- epilogue: bias add + direct float2 stores (row-permuted C) ----
    const int col_l = nbase + col_w;
    float2 bv[4];
#pragma unroll
    for (int nt = 0; nt < 4; ++nt)
        bv[nt] = *reinterpret_cast<const float2*>(bias + col_l + nt * 8);

    const int Rbase = by * GM + wm * 64 + (lane >> 2);
#pragma unroll
    for (int mt = 0; mt < 4; ++mt) {
        const size_t r0 = (size_t)crow(Rbase + mt * 16)     * VOCAB;
        const size_t r1 = (size_t)crow(Rbase + mt * 16 + 8) * VOCAB;
#pragma unroll
        for (int nt = 0; nt < 4; ++nt) {
            float2 v0 = make_float2(acc[mt][nt][0] + bv[nt].x,
                                    acc[mt][nt][1] + bv[nt].y);
            float2 v1 = make_float2(acc[mt][nt][2] + bv[nt].x,
                                    acc[mt][nt][3] + bv[nt].y);
            *reinterpret_cast<float2*>(C + r0 + col_l + nt * 8) = v0;
            *reinterpret_cast<float2*>(C + r1 + col_l + nt * 8) = v1;
        }
    }
}

// ---------------------------------------------------------------------------
// Launch
// Inputs: 0 tokens(int32) 1 emb 2 w_ih 3 w_hh 4 b_ih 5 b_hh 6 w_out 7 b_out
// ---------------------------------------------------------------------------
extern "C" void kernel_launch(void* const* d_in, const int* in_sizes, int n_in,
                              void* d_out, int out_size)
{
    const int*   tokens = (const int*)  d_in[0];
    const float* emb    = (const float*)d_in[1];
    const float* w_ih   = (const float*)d_in[2];
    const float* w_hh   = (const float*)d_in[3];
    const float* b_ih   = (const float*)d_in[4];
    const float* b_hh   = (const float*)d_in[5];
    const float* w_out  = (const float*)d_in[6];
    const float* b_out  = (const float*)d_in[7];
    float* out = (float*)d_out;

    (void)in_sizes; (void)n_in; (void)out_size;

    cudaFuncSetAttribute(fat_kernel,
                         cudaFuncAttributeMaxDynamicSharedMemorySize, TILE_SM);

    prep_kernel<<<WCONV_BLOCKS + ROWS / 32, 256>>>(w_out, tokens, emb, w_ih, b_ih);
    fat_kernel<<<GRID_FAT, 256, TILE_SM>>>(w_hh, b_hh, b_out, out);
}